// round 13
// baseline (speedup 1.0000x reference)
#include <cuda_runtime.h>
#include <cuda_bf16.h>
#include <cstdint>

#define HID    256
#define BATCH  64
#define TT     256
#define INDIM  64
#define OUTDIM 32

#define OUT_ELEMS   (BATCH*TT*OUTDIM)          // 524288
#define XF_OFF      OUT_ELEMS
#define TRAJ_OFF    (OUT_ELEMS + BATCH*HID)    // 540672

#define NCTA 128
#define NTHR 256

// ---------------- device globals (static scratch; no runtime allocation) ----------------
__device__ __nv_bfloat16 g_Wb[(size_t)HID * HID * HID];      // 33.5 MB bf16 W tensor [j][i][k]
__device__ float         g_Ieff[(size_t)TT * BATCH * HID];   // 16.8 MB
__device__ float         g_x[BATCH * HID];                   // state x [b][j]
__device__ __nv_bfloat16 g_rb[2][BATCH * HID];               // double-buffered r = tanh(x)
__device__ unsigned      g_barcnt = 0;
__device__ unsigned      g_bargen = 0;

// ---------------- mma helper (bf16 -> fp32, m16n8k16) ----------------
__device__ __forceinline__ void mma16816(float c[4], const unsigned a[4], const unsigned b[2]) {
    asm volatile(
        "mma.sync.aligned.m16n8k16.row.col.f32.bf16.bf16.f32 "
        "{%0,%1,%2,%3}, {%4,%5,%6,%7}, {%8,%9}, {%0,%1,%2,%3};\n"
        : "+f"(c[0]), "+f"(c[1]), "+f"(c[2]), "+f"(c[3])
        : "r"(a[0]), "r"(a[1]), "r"(a[2]), "r"(a[3]), "r"(b[0]), "r"(b[1]));
}

// ---------------- software grid barrier (all CTAs resident) ----------------
__device__ __forceinline__ void gridbar() {
    __syncthreads();
    __threadfence();
    if (threadIdx.x == 0) {
        unsigned gen  = atomicAdd(&g_bargen, 0u);
        unsigned prev = atomicAdd(&g_barcnt, 1u);
        if (prev == gridDim.x - 1u) {
            atomicExch(&g_barcnt, 0u);
            __threadfence();
            atomicAdd(&g_bargen, 1u);
        } else {
            while (atomicAdd(&g_bargen, 0u) == gen) { __nanosleep(64); }
        }
    }
    __threadfence();
    __syncthreads();
}

// ---------------- prologue: fp32 W -> bf16 ----------------
__global__ void k_conv(const float* __restrict__ W) {
    size_t i = (size_t)blockIdx.x * blockDim.x + threadIdx.x;
    size_t n2 = (size_t)HID * HID * HID / 2;
    if (i < n2) {
        float2 v = ((const float2*)W)[i];
        ((__nv_bfloat162*)g_Wb)[i] = __floats2bfloat162_rn(v.x, v.y);
    }
}

// ---------------- prologue: init state ----------------
__global__ void k_init(const float* __restrict__ x0) {
    int i = blockIdx.x * blockDim.x + threadIdx.x;
    if (i < BATCH * HID) {
        float v = x0[i];
        g_x[i] = v;
        g_rb[0][i] = __float2bfloat16(tanhf(v));
    }
}

// ---------------- prologue: Ieff[t][b][h] = 0.05*noise + 0.2*(u[b,t,:]@win[h,:] + winb[h]) ----------------
__global__ void k_ieff(const float* __restrict__ u, const float* __restrict__ noise,
                       const float* __restrict__ winw, const float* __restrict__ winb) {
    __shared__ float us[BATCH][INDIM];  // 16 KB
    int t = blockIdx.x;
    int h = threadIdx.x;
    for (int idx = h; idx < BATCH * INDIM; idx += blockDim.x) {
        int b = idx / INDIM, in = idx % INDIM;
        us[b][in] = u[((size_t)b * TT + t) * INDIM + in];
    }
    __syncthreads();
    float wreg[INDIM];
    #pragma unroll
    for (int in = 0; in < INDIM; ++in) wreg[in] = winw[h * INDIM + in];
    float bias = winb[h];
    for (int b = 0; b < BATCH; ++b) {
        float acc = bias;
        #pragma unroll
        for (int in = 0; in < INDIM; ++in) acc += us[b][in] * wreg[in];
        size_t off = ((size_t)t * BATCH + b) * HID + h;
        g_Ieff[off] = 0.05f * noise[off] + 0.2f * acc;
    }
}

// ---------------- main persistent kernel ----------------
__global__ void __launch_bounds__(NTHR, 1)
k_main(const float* __restrict__ whh_g, float* __restrict__ dout) {
    __shared__ __nv_bfloat16 rs[64 * 264];   // padded rows (264 bf16 = 528B stride) -> bank-conflict-free
    __shared__ float reds[8][64];
    __shared__ float w2s[2][64];
    __shared__ float whh[2][HID];

    const int tid  = threadIdx.x;
    const int warp = tid >> 5;
    const int lane = tid & 31;
    const int lq   = lane >> 2;   // 0..7
    const int lr   = lane & 3;    // 0..3
    const int j0   = blockIdx.x * 2;
    const int nbase = warp * 32;

    const uint32_t* rsw = (const uint32_t*)rs;
    float* traj = dout + TRAJ_OFF;

    // preload w_hh_rnn rows j0, j0+1
    whh[0][tid] = whh_g[(size_t)j0 * HID + tid];
    whh[1][tid] = whh_g[(size_t)(j0 + 1) * HID + tid];

    int cur = 0;
    for (int t = 0; t < TT; ++t) {
        // stage r[cur] into padded smem
        const uint4* src = (const uint4*)g_rb[cur];
        #pragma unroll
        for (int idx = tid; idx < 64 * 32; idx += NTHR) {
            int row = idx >> 5, c = idx & 31;
            ((uint4*)rs)[row * 33 + c] = src[idx];   // 33 uint4 = 264 bf16 stride
        }
        __syncthreads();

        // ---- per owned j: GEMM C[b,i] = sum_k r[b,k] * W[j,i,k], fused W2 epilogue ----
        for (int jj = 0; jj < 2; ++jj) {
            const int j = j0 + jj;
            const uint32_t* Wjw = (const uint32_t*)(g_Wb + (size_t)j * (HID * HID));

            float acc[4][4][4];
            #pragma unroll
            for (int m = 0; m < 4; ++m)
                #pragma unroll
                for (int n = 0; n < 4; ++n)
                    #pragma unroll
                    for (int f = 0; f < 4; ++f) acc[m][n][f] = 0.f;

            #pragma unroll 4
            for (int kt = 0; kt < 16; ++kt) {
                const int k0 = kt * 16 + lr * 2;
                unsigned a[4][4];
                #pragma unroll
                for (int m = 0; m < 4; ++m) {
                    int r0 = m * 16 + lq;
                    a[m][0] = rsw[r0 * 132 + (k0 >> 1)];
                    a[m][1] = rsw[(r0 + 8) * 132 + (k0 >> 1)];
                    a[m][2] = rsw[r0 * 132 + ((k0 + 8) >> 1)];
                    a[m][3] = rsw[(r0 + 8) * 132 + ((k0 + 8) >> 1)];
                }
                unsigned bf[4][2];
                #pragma unroll
                for (int n = 0; n < 4; ++n) {
                    int nc = nbase + n * 8 + lq;            // i index
                    bf[n][0] = __ldg(&Wjw[(nc * HID + k0) >> 1]);
                    bf[n][1] = __ldg(&Wjw[(nc * HID + k0 + 8) >> 1]);
                }
                #pragma unroll
                for (int m = 0; m < 4; ++m)
                    #pragma unroll
                    for (int n = 0; n < 4; ++n)
                        mma16816(acc[m][n], a[m], bf[n]);
            }

            // epilogue: p[b] = sum_i r[b,i]*C[b,i] (per-thread partials)
            float p[8];
            #pragma unroll
            for (int m = 0; m < 8; ++m) p[m] = 0.f;
            #pragma unroll
            for (int m = 0; m < 4; ++m) {
                int b0 = m * 16 + lq, b1 = b0 + 8;
                #pragma unroll
                for (int n = 0; n < 4; ++n) {
                    int i0 = nbase + n * 8 + lr * 2;
                    float r00 = __bfloat162float(rs[b0 * 264 + i0]);
                    float r01 = __bfloat162float(rs[b0 * 264 + i0 + 1]);
                    float r10 = __bfloat162float(rs[b1 * 264 + i0]);
                    float r11 = __bfloat162float(rs[b1 * 264 + i0 + 1]);
                    p[2 * m]     += acc[m][n][0] * r00 + acc[m][n][1] * r01;
                    p[2 * m + 1] += acc[m][n][2] * r10 + acc[m][n][3] * r11;
                }
            }
            #pragma unroll
            for (int m = 0; m < 8; ++m) {
                p[m] += __shfl_xor_sync(0xFFFFFFFFu, p[m], 1);
                p[m] += __shfl_xor_sync(0xFFFFFFFFu, p[m], 2);
            }
            if (lr == 0) {
                #pragma unroll
                for (int m = 0; m < 4; ++m) {
                    reds[warp][m * 16 + lq]     = p[2 * m];
                    reds[warp][m * 16 + lq + 8] = p[2 * m + 1];
                }
            }
            __syncthreads();
            if (tid < 64) {
                float s = 0.f;
                #pragma unroll
                for (int w = 0; w < 8; ++w) s += reds[w][tid];
                w2s[jj][tid] = s;
            }
            __syncthreads();
        }

        // ---- W1 + state update for owned (jj,b) pairs ----
        if (tid < 128) {
            int jj = tid >> 6, b = tid & 63, j = j0 + jj;
            float w1 = 0.f;
            const uint32_t* rrow = rsw + b * 132;
            #pragma unroll 8
            for (int i2 = 0; i2 < 128; ++i2) {
                uint32_t rv = rrow[i2];
                __nv_bfloat162 r2 = *(__nv_bfloat162*)&rv;
                w1 += __bfloat162float(r2.x) * whh[jj][2 * i2]
                    + __bfloat162float(r2.y) * whh[jj][2 * i2 + 1];
            }
            float xo = g_x[b * HID + j];
            float xn = 0.8f * xo
                     + g_Ieff[((size_t)t * BATCH + b) * HID + j]
                     + 0.2f * (w1 + w2s[jj][b]);
            g_x[b * HID + j] = xn;
            traj[((size_t)b * TT + t) * HID + j] = xn;
            g_rb[cur ^ 1][b * HID + j] = __float2bfloat16(tanhf(xn));
        }

        gridbar();
        cur ^= 1;
    }
}

// ---------------- epilogue: output head ----------------
__global__ void k_head(const float* __restrict__ wo, const float* __restrict__ wob,
                       float* __restrict__ dout) {
    __shared__ float sh[HID];
    __shared__ float red[256];
    int row = blockIdx.x;  // b*TT + t
    const float* tr = dout + TRAJ_OFF + (size_t)row * HID;
    int tid = threadIdx.x;
    sh[tid] = tanhf(tr[tid]);
    __syncthreads();
    int o = tid & 31, sl = tid >> 5;
    float p = 0.f;
    const float* w = wo + o * HID + sl * 32;
    const float* s = sh + sl * 32;
    #pragma unroll
    for (int i = 0; i < 32; ++i) p += s[i] * __ldg(&w[i]);
    red[tid] = p;
    __syncthreads();
    if (tid < 32) {
        float s2 = red[tid];
        #pragma unroll
        for (int k = 1; k < 8; ++k) s2 += red[tid + 32 * k];
        dout[(size_t)row * OUTDIM + tid] = s2 + wob[tid];
    }
}

// ---------------- epilogue: x_final copy ----------------
__global__ void k_xf(float* __restrict__ dout) {
    int i = blockIdx.x * blockDim.x + threadIdx.x;
    if (i < BATCH * HID) dout[XF_OFF + i] = g_x[i];
}

extern "C" void kernel_launch(void* const* d_in, const int* in_sizes, int n_in,
                              void* d_out, int out_size) {
    const float* u      = (const float*)d_in[0];
    const float* x0     = (const float*)d_in[1];
    const float* noise  = (const float*)d_in[2];
    const float* whh    = (const float*)d_in[3];
    const float* wtb    = (const float*)d_in[4];
    const float* winw   = (const float*)d_in[5];
    const float* winb   = (const float*)d_in[6];
    const float* woutw  = (const float*)d_in[7];
    const float* woutb  = (const float*)d_in[8];
    float* dout = (float*)d_out;

    k_conv<<<32768, 256>>>(wtb);
    k_init<<<64, 256>>>(x0);
    k_ieff<<<TT, HID>>>(u, noise, winw, winb);
    k_main<<<NCTA, NTHR>>>(whh, dout);
    k_head<<<BATCH * TT, HID>>>(woutw, woutb, dout);
    k_xf<<<64, 256>>>(dout);
}

// round 14
// speedup vs baseline: 1.6379x; 1.6379x over previous
#include <cuda_runtime.h>
#include <cuda_bf16.h>
#include <cstdint>

#define HID    256
#define BATCH  64
#define TT     256
#define INDIM  64
#define OUTDIM 32

#define OUT_ELEMS   (BATCH*TT*OUTDIM)
#define XF_OFF      OUT_ELEMS
#define TRAJ_OFF    (OUT_ELEMS + BATCH*HID)

#define NCTA 128
#define NTHR 256
#define BUF0 33792u
#define BUF1 54272u
#define DSMEM 74752u

__device__ __nv_bfloat16 g_Wb[(size_t)HID * HID * HID];      // bf16 W [j][i][k]
__device__ float         g_Ieff[(size_t)TT * BATCH * HID];
__device__ float         g_x[BATCH * HID];
__device__ __nv_bfloat16 g_rb[2][BATCH * HID];
__device__ unsigned      g_barcnt = 0;
__device__ unsigned      g_bargen = 0;

__device__ __forceinline__ void mma16816(float c[4], const unsigned a[4], const unsigned b[2]) {
    asm volatile(
        "mma.sync.aligned.m16n8k16.row.col.f32.bf16.bf16.f32 "
        "{%0,%1,%2,%3}, {%4,%5,%6,%7}, {%8,%9}, {%0,%1,%2,%3};\n"
        : "+f"(c[0]), "+f"(c[1]), "+f"(c[2]), "+f"(c[3])
        : "r"(a[0]), "r"(a[1]), "r"(a[2]), "r"(a[3]), "r"(b[0]), "r"(b[1]));
}

__device__ __forceinline__ void cp16(char* sm, unsigned off, const void* g) {
    unsigned sa = (unsigned)__cvta_generic_to_shared(sm + off);
    asm volatile("cp.async.cg.shared.global [%0], [%1], 16;\n" :: "r"(sa), "l"(g));
}

__device__ __forceinline__ void gridbar() {
    __syncthreads();
    __threadfence();
    if (threadIdx.x == 0) {
        unsigned gen  = atomicAdd(&g_bargen, 0u);
        unsigned prev = atomicAdd(&g_barcnt, 1u);
        if (prev == gridDim.x - 1u) {
            atomicExch(&g_barcnt, 0u);
            __threadfence();
            atomicAdd(&g_bargen, 1u);
        } else {
            while (atomicAdd(&g_bargen, 0u) == gen) { __nanosleep(64); }
        }
    }
    __threadfence();
    __syncthreads();
}

__global__ void k_conv(const float* __restrict__ W) {
    size_t i = (size_t)blockIdx.x * blockDim.x + threadIdx.x;
    size_t n2 = (size_t)HID * HID * HID / 2;
    if (i < n2) {
        float2 v = ((const float2*)W)[i];
        ((__nv_bfloat162*)g_Wb)[i] = __floats2bfloat162_rn(v.x, v.y);
    }
}

__global__ void k_init(const float* __restrict__ x0) {
    int i = blockIdx.x * blockDim.x + threadIdx.x;
    if (i < BATCH * HID) {
        float v = x0[i];
        g_x[i] = v;
        g_rb[0][i] = __float2bfloat16(tanhf(v));
    }
}

__global__ void k_ieff(const float* __restrict__ u, const float* __restrict__ noise,
                       const float* __restrict__ winw, const float* __restrict__ winb) {
    __shared__ float us[BATCH][INDIM];
    int t = blockIdx.x, h = threadIdx.x;
    for (int idx = h; idx < BATCH * INDIM; idx += blockDim.x) {
        int b = idx / INDIM, in = idx % INDIM;
        us[b][in] = u[((size_t)b * TT + t) * INDIM + in];
    }
    __syncthreads();
    float wreg[INDIM];
    #pragma unroll
    for (int in = 0; in < INDIM; ++in) wreg[in] = winw[h * INDIM + in];
    float bias = winb[h];
    for (int b = 0; b < BATCH; ++b) {
        float acc = bias;
        #pragma unroll
        for (int in = 0; in < INDIM; ++in) acc += us[b][in] * wreg[in];
        size_t off = ((size_t)t * BATCH + b) * HID + h;
        g_Ieff[off] = 0.05f * noise[off] + 0.2f * acc;
    }
}

__global__ void __launch_bounds__(NTHR, 1)
k_main(const float* __restrict__ whh_g, float* __restrict__ dout) {
    extern __shared__ char smem[];                 // [0,33792): rs ; tiles at BUF0/BUF1
    __shared__ float reds[4][64];
    __shared__ float w2s[2][64];
    __shared__ float whh[2][HID];

    __nv_bfloat16* rs = (__nv_bfloat16*)smem;      // 64 rows x 264 bf16 (528B stride)
    const uint32_t* rsw = (const uint32_t*)smem;   // 132 words per row

    const int tid  = threadIdx.x;
    const int warp = tid >> 5;
    const int lane = tid & 31;
    const int lq   = lane >> 2, lr = lane & 3;
    const int j0   = blockIdx.x * 2;
    float* traj = dout + TRAJ_OFF;

    whh[0][tid] = whh_g[(size_t)j0 * HID + tid];
    whh[1][tid] = whh_g[(size_t)(j0 + 1) * HID + tid];

    int cur = 0;
    for (int t = 0; t < TT; ++t) {
        // ---- stage r into padded smem ----
        const uint4* src = (const uint4*)g_rb[cur];
        #pragma unroll
        for (int it = 0; it < 8; ++it) {
            int idx = it * 256 + tid, row = idx >> 5, c = idx & 31;
            ((uint4*)rs)[row * 33 + c] = src[idx];
        }
        // ---- prefetch W tile 0 (jj=0, kc=0) ----
        {
            const char* wsrc = (const char*)g_Wb + (size_t)j0 * 131072;
            #pragma unroll
            for (int it = 0; it < 4; ++it) {
                int idx = it * 256 + tid, i = idx >> 2, c = idx & 3;
                cp16(smem, BUF0 + (unsigned)(i * 80 + c * 16), wsrc + (size_t)i * 512 + c * 16);
            }
            asm volatile("cp.async.commit_group;\n" ::);
        }
        asm volatile("cp.async.wait_group 0;\n" ::: "memory");
        __syncthreads();

        float acc[4][8][4];
        for (int tt = 0; tt < 16; ++tt) {
            const int jj = tt >> 3, kc = tt & 7;
            if (kc == 0) {
                #pragma unroll
                for (int m = 0; m < 4; ++m)
                    #pragma unroll
                    for (int n = 0; n < 8; ++n)
                        #pragma unroll
                        for (int f = 0; f < 4; ++f) acc[m][n][f] = 0.f;
            }
            if (tt < 15) {       // prefetch next tile into other buffer
                int nn = tt + 1;
                const char* wsrc = (const char*)g_Wb
                    + (size_t)(j0 + (nn >> 3)) * 131072 + (size_t)(nn & 7) * 64;
                unsigned dbase = (nn & 1) ? BUF1 : BUF0;
                #pragma unroll
                for (int it = 0; it < 4; ++it) {
                    int idx = it * 256 + tid, i = idx >> 2, c = idx & 3;
                    cp16(smem, dbase + (unsigned)(i * 80 + c * 16), wsrc + (size_t)i * 512 + c * 16);
                }
                asm volatile("cp.async.commit_group;\n" ::);
                asm volatile("cp.async.wait_group 1;\n" ::: "memory");
            } else {
                asm volatile("cp.async.wait_group 0;\n" ::: "memory");
            }
            __syncthreads();

            if (warp < 4) {      // mma warps: i-range = warp*64 .. +63
                const uint32_t* wt = (const uint32_t*)(smem + ((tt & 1) ? BUF1 : BUF0));
                #pragma unroll
                for (int l = 0; l < 2; ++l) {
                    const int gkt = kc * 2 + l;
                    const int k0 = gkt * 16 + lr * 2;
                    unsigned a[4][4];
                    #pragma unroll
                    for (int m = 0; m < 4; ++m) {
                        int r0 = m * 16 + lq;
                        a[m][0] = rsw[r0 * 132 + (k0 >> 1)];
                        a[m][1] = rsw[(r0 + 8) * 132 + (k0 >> 1)];
                        a[m][2] = rsw[r0 * 132 + ((k0 + 8) >> 1)];
                        a[m][3] = rsw[(r0 + 8) * 132 + ((k0 + 8) >> 1)];
                    }
                    unsigned bf[8][2];
                    #pragma unroll
                    for (int n = 0; n < 8; ++n) {
                        int row = warp * 64 + n * 8 + lq;      // i index
                        bf[n][0] = wt[row * 20 + l * 8 + lr];
                        bf[n][1] = wt[row * 20 + l * 8 + lr + 4];
                    }
                    #pragma unroll
                    for (int m = 0; m < 4; ++m)
                        #pragma unroll
                        for (int n = 0; n < 8; ++n)
                            mma16816(acc[m][n], a[m], bf[n]);
                }
            }
            __syncthreads();     // protect buffer reuse before next prefetch

            if (kc == 7) {       // fused W2 epilogue for this jj
                if (warp < 4) {
                    float p[8];
                    #pragma unroll
                    for (int m = 0; m < 8; ++m) p[m] = 0.f;
                    #pragma unroll
                    for (int m = 0; m < 4; ++m) {
                        int b0 = m * 16 + lq, b1 = b0 + 8;
                        #pragma unroll
                        for (int n = 0; n < 8; ++n) {
                            int i0 = warp * 64 + n * 8 + lr * 2;
                            float r00 = __bfloat162float(rs[b0 * 264 + i0]);
                            float r01 = __bfloat162float(rs[b0 * 264 + i0 + 1]);
                            float r10 = __bfloat162float(rs[b1 * 264 + i0]);
                            float r11 = __bfloat162float(rs[b1 * 264 + i0 + 1]);
                            p[2*m]   += acc[m][n][0] * r00 + acc[m][n][1] * r01;
                            p[2*m+1] += acc[m][n][2] * r10 + acc[m][n][3] * r11;
                        }
                    }
                    #pragma unroll
                    for (int m = 0; m < 8; ++m) {
                        p[m] += __shfl_xor_sync(0xFFFFFFFFu, p[m], 1);
                        p[m] += __shfl_xor_sync(0xFFFFFFFFu, p[m], 2);
                    }
                    if (lr == 0) {
                        #pragma unroll
                        for (int m = 0; m < 4; ++m) {
                            reds[warp][m * 16 + lq]     = p[2*m];
                            reds[warp][m * 16 + lq + 8] = p[2*m+1];
                        }
                    }
                }
                __syncthreads();
                if (tid < 64) {
                    w2s[jj][tid] = reds[0][tid] + reds[1][tid] + reds[2][tid] + reds[3][tid];
                }
                __syncthreads();
            }
        }

        // ---- W1 + state update ----
        if (tid < 128) {
            int jj = tid >> 6, b = tid & 63, j = j0 + jj;
            float w1 = 0.f;
            const uint32_t* rrow = rsw + b * 132;
            #pragma unroll 8
            for (int i2 = 0; i2 < 128; ++i2) {
                uint32_t rv = rrow[i2];
                __nv_bfloat162 r2 = *(__nv_bfloat162*)&rv;
                w1 += __bfloat162float(r2.x) * whh[jj][2*i2]
                    + __bfloat162float(r2.y) * whh[jj][2*i2 + 1];
            }
            float xo = g_x[b * HID + j];
            float xn = 0.8f * xo
                     + g_Ieff[((size_t)t * BATCH + b) * HID + j]
                     + 0.2f * (w1 + w2s[jj][b]);
            g_x[b * HID + j] = xn;
            traj[((size_t)b * TT + t) * HID + j] = xn;
            g_rb[cur ^ 1][b * HID + j] = __float2bfloat16(tanhf(xn));
        }

        gridbar();
        cur ^= 1;
    }
}

__global__ void k_head(const float* __restrict__ wo, const float* __restrict__ wob,
                       float* __restrict__ dout) {
    __shared__ float sh[HID];
    __shared__ float red[256];
    int row = blockIdx.x;
    const float* tr = dout + TRAJ_OFF + (size_t)row * HID;
    int tid = threadIdx.x;
    sh[tid] = tanhf(tr[tid]);
    __syncthreads();
    int o = tid & 31, sl = tid >> 5;
    float p = 0.f;
    const float* w = wo + o * HID + sl * 32;
    const float* s = sh + sl * 32;
    #pragma unroll
    for (int i = 0; i < 32; ++i) p += s[i] * __ldg(&w[i]);
    red[tid] = p;
    __syncthreads();
    if (tid < 32) {
        float s2 = red[tid];
        #pragma unroll
        for (int k = 1; k < 8; ++k) s2 += red[tid + 32 * k];
        dout[(size_t)row * OUTDIM + tid] = s2 + wob[tid];
    }
}

__global__ void k_xf(float* __restrict__ dout) {
    int i = blockIdx.x * blockDim.x + threadIdx.x;
    if (i < BATCH * HID) dout[XF_OFF + i] = g_x[i];
}

extern "C" void kernel_launch(void* const* d_in, const int* in_sizes, int n_in,
                              void* d_out, int out_size) {
    const float* u      = (const float*)d_in[0];
    const float* x0     = (const float*)d_in[1];
    const float* noise  = (const float*)d_in[2];
    const float* whh    = (const float*)d_in[3];
    const float* wtb    = (const float*)d_in[4];
    const float* winw   = (const float*)d_in[5];
    const float* winb   = (const float*)d_in[6];
    const float* woutw  = (const float*)d_in[7];
    const float* woutb  = (const float*)d_in[8];
    float* dout = (float*)d_out;

    static int smem_set = 0;
    if (!smem_set) {
        cudaFuncSetAttribute(k_main, cudaFuncAttributeMaxDynamicSharedMemorySize, DSMEM);
        smem_set = 1;
    }

    k_conv<<<32768, 256>>>(wtb);
    k_init<<<64, 256>>>(x0);
    k_ieff<<<TT, HID>>>(u, noise, winw, winb);
    k_main<<<NCTA, NTHR, DSMEM>>>(whh, dout);
    k_head<<<BATCH * TT, HID>>>(woutw, woutb, dout);
    k_xf<<<64, 256>>>(dout);
}

// round 15
// speedup vs baseline: 2.8673x; 1.7506x over previous
#include <cuda_runtime.h>
#include <cuda_bf16.h>
#include <cstdint>

#define HID 256
#define BATCH 64
#define TT 256
#define INDIM 64
#define OUTDIM 32
#define OUT_ELEMS (BATCH*TT*OUTDIM)
#define XF_OFF OUT_ELEMS
#define TRAJ_OFF (OUT_ELEMS + BATCH*HID)
#define NCTA 128
#define NTHR 256
#define RS_OFF 139264u
#define DSMEM (139264u + 33792u)   // T tiles + padded rs = 173056

__device__ __nv_bfloat16 g_Tb[(size_t)256 * 34816];        // 17.8 MB packed sym tiles
__device__ float         g_Ieff[(size_t)TT * BATCH * HID];
__device__ __nv_bfloat16 g_rb[2][BATCH * HID];
__device__ volatile unsigned g_flags[NCTA];
__device__ volatile unsigned g_rel;

__device__ __forceinline__ void mma16816(float c[4], const unsigned a[4], const unsigned b[2]) {
    asm volatile(
        "mma.sync.aligned.m16n8k16.row.col.f32.bf16.bf16.f32 "
        "{%0,%1,%2,%3}, {%4,%5,%6,%7}, {%8,%9}, {%0,%1,%2,%3};\n"
        : "+f"(c[0]), "+f"(c[1]), "+f"(c[2]), "+f"(c[3])
        : "r"(a[0]), "r"(a[1]), "r"(a[2]), "r"(a[3]), "r"(b[0]), "r"(b[1]));
}

__device__ __forceinline__ void cp16(char* sm, unsigned off, const void* g) {
    unsigned sa = (unsigned)__cvta_generic_to_shared(sm + off);
    asm volatile("cp.async.cg.shared.global [%0], [%1], 16;\n" :: "r"(sa), "l"(g));
}

__global__ void k_init(const float* __restrict__ x0) {
    int i = blockIdx.x * blockDim.x + threadIdx.x;
    if (i < BATCH * HID) g_rb[0][i] = __float2bfloat16(tanhf(x0[i]));
}

__global__ void k_ieff(const float* __restrict__ u, const float* __restrict__ noise,
                       const float* __restrict__ winw, const float* __restrict__ winb) {
    __shared__ float us[BATCH][INDIM];
    int t = blockIdx.x, h = threadIdx.x;
    for (int idx = h; idx < BATCH * INDIM; idx += blockDim.x) {
        int b = idx / INDIM, in = idx % INDIM;
        us[b][in] = u[((size_t)b * TT + t) * INDIM + in];
    }
    __syncthreads();
    float wreg[INDIM];
    #pragma unroll
    for (int in = 0; in < INDIM; ++in) wreg[in] = winw[h * INDIM + in];
    float bias = winb[h];
    for (int b = 0; b < BATCH; ++b) {
        float acc = bias;
        #pragma unroll
        for (int in = 0; in < INDIM; ++in) acc += us[b][in] * wreg[in];
        size_t off = ((size_t)t * BATCH + b) * HID + h;
        g_Ieff[off] = 0.05f * noise[off] + 0.2f * acc;
    }
}

// pack T[j, tile(I,K)] = (W[j,i,k] + W[j,k,i]) (diag tiles *0.5), TRANSPOSED [k][i], swizzled
__global__ void k_pack(const float* __restrict__ W) {
    int t = blockIdx.x, j = blockIdx.y;
    int i = threadIdx.x & 15, k = threadIdx.x >> 4;
    int K = 0;
    while ((K + 1) * (K + 2) / 2 <= t) ++K;
    int I = t - K * (K + 1) / 2;
    size_t base = (size_t)j * 65536;
    float v = W[base + (size_t)(I * 16 + i) * 256 + K * 16 + k]
            + W[base + (size_t)(K * 16 + k) * 256 + I * 16 + i];
    if (I == K) v *= 0.5f;
    int iw = (i >> 1) ^ ((k & 4) ? 4 : 0);
    g_Tb[(size_t)j * 34816 + t * 256 + k * 16 + iw * 2 + (i & 1)] = __float2bfloat16(v);
}

__global__ void __launch_bounds__(NTHR, 1)
k_main(const float* __restrict__ whh_g, const float* __restrict__ x0,
       float* __restrict__ dout) {
    extern __shared__ char smem[];
    const uint32_t* Tsm = (const uint32_t*)smem;                // 272 tiles * 128 words
    const uint32_t* rsw = (const uint32_t*)(smem + RS_OFF);     // 64 rows * 132 words (528B)
    __shared__ float reds[8][64];
    __shared__ float whh[2][HID];
    __shared__ unsigned sbase;

    const int tid = threadIdx.x, warp = tid >> 5, lane = tid & 31;
    const int lq = lane >> 2, lr = lane & 3;
    const int j0 = blockIdx.x * 2;
    const int ww = warp & 3, jsel = warp >> 2;
    float* traj = dout + TRAJ_OFF;

    if (tid == 0) sbase = g_rel;
    whh[0][tid] = whh_g[(size_t)j0 * HID + tid];
    whh[1][tid] = whh_g[(size_t)(j0 + 1) * HID + tid];

    // one-time load of T[j0],T[j1] (139264B) into smem
    {
        const char* src = (const char*)(g_Tb + (size_t)j0 * 34816);
        #pragma unroll
        for (int it = 0; it < 34; ++it) {
            int idx = it * 256 + tid;
            cp16(smem, (unsigned)idx * 16u, src + (size_t)idx * 16);
        }
        asm volatile("cp.async.commit_group;\n" ::);
    }
    float xv = 0.f;
    if (tid < 128) xv = x0[(size_t)(tid & 63) * HID + j0 + (tid >> 6)];

    const int cols[4] = { ww, 15 - ww, ww + 4, 11 - ww };
    const int m4 = (lq & 4) ? 4 : 0;

    int cur = 0;
    for (int t = 0; t < TT; ++t) {
        // stage r (bf16, padded rows) via cp.async
        const char* src = (const char*)g_rb[cur];
        #pragma unroll
        for (int it = 0; it < 8; ++it) {
            int idx = it * 256 + tid, row = idx >> 5, c = idx & 31;
            cp16(smem, RS_OFF + (unsigned)(row * 528 + c * 16), src + (size_t)idx * 16);
        }
        asm volatile("cp.async.commit_group;\n" ::);
        asm volatile("cp.async.wait_group 0;\n" ::: "memory");
        __syncthreads();

        float p[8];
        #pragma unroll
        for (int m = 0; m < 8; ++m) p[m] = 0.f;

        #pragma unroll
        for (int cc = 0; cc < 4; ++cc) {
            const int K = cols[cc];
            float acc[4][2][4];
            #pragma unroll
            for (int m = 0; m < 4; ++m)
                #pragma unroll
                for (int g = 0; g < 2; ++g)
                    #pragma unroll
                    for (int f = 0; f < 4; ++f) acc[m][g][f] = 0.f;

            const uint32_t* tbase = Tsm + (size_t)(jsel * 136 + K * (K + 1) / 2) * 128;
            for (int I = 0; I <= K; ++I) {
                const uint32_t* tw = tbase + I * 128;
                unsigned a[4][4];
                #pragma unroll
                for (int m = 0; m < 4; ++m) {
                    int r0 = m * 16 + lq;
                    a[m][0] = rsw[r0 * 132 + I * 8 + lr];
                    a[m][1] = rsw[(r0 + 8) * 132 + I * 8 + lr];
                    a[m][2] = rsw[r0 * 132 + I * 8 + lr + 4];
                    a[m][3] = rsw[(r0 + 8) * 132 + I * 8 + lr + 4];
                }
                unsigned bf[2][2];
                bf[0][0] = tw[lq * 8 + (lr ^ m4)];
                bf[0][1] = tw[lq * 8 + ((lr + 4) ^ m4)];
                bf[1][0] = tw[(lq + 8) * 8 + (lr ^ m4)];
                bf[1][1] = tw[(lq + 8) * 8 + ((lr + 4) ^ m4)];
                #pragma unroll
                for (int m = 0; m < 4; ++m) {
                    mma16816(acc[m][0], a[m], bf[0]);
                    mma16816(acc[m][1], a[m], bf[1]);
                }
            }
            // column epilogue: p[b] += y_K[b,:] . r[b, K-block]
            #pragma unroll
            for (int m = 0; m < 4; ++m) {
                int b0 = m * 16 + lq;
                #pragma unroll
                for (int g = 0; g < 2; ++g) {
                    uint32_t rv0 = rsw[b0 * 132 + K * 8 + g * 4 + lr];
                    uint32_t rv1 = rsw[(b0 + 8) * 132 + K * 8 + g * 4 + lr];
                    __nv_bfloat162 q0 = *(__nv_bfloat162*)&rv0;
                    __nv_bfloat162 q1 = *(__nv_bfloat162*)&rv1;
                    p[2 * m]     += acc[m][g][0] * __bfloat162float(q0.x) + acc[m][g][1] * __bfloat162float(q0.y);
                    p[2 * m + 1] += acc[m][g][2] * __bfloat162float(q1.x) + acc[m][g][3] * __bfloat162float(q1.y);
                }
            }
        }
        #pragma unroll
        for (int m = 0; m < 8; ++m) {
            p[m] += __shfl_xor_sync(0xFFFFFFFFu, p[m], 1);
            p[m] += __shfl_xor_sync(0xFFFFFFFFu, p[m], 2);
        }
        if (lr == 0) {
            #pragma unroll
            for (int m = 0; m < 4; ++m) {
                reds[warp][m * 16 + lq]     = p[2 * m];
                reds[warp][m * 16 + lq + 8] = p[2 * m + 1];
            }
        }
        __syncthreads();

        // W1 + state update (writer thread == reducer thread; no extra sync)
        if (tid < 128) {
            int jj = tid >> 6, b = tid & 63, j = j0 + jj;
            float w2 = reds[jj * 4][b] + reds[jj * 4 + 1][b] + reds[jj * 4 + 2][b] + reds[jj * 4 + 3][b];
            float w1 = 0.f;
            const uint32_t* rrow = rsw + b * 132;
            const float* wh = whh[jj];
            #pragma unroll 16
            for (int i2 = 0; i2 < 128; ++i2) {
                uint32_t rv = rrow[i2];
                __nv_bfloat162 r2 = *(__nv_bfloat162*)&rv;
                w1 += __bfloat162float(r2.x) * wh[2 * i2] + __bfloat162float(r2.y) * wh[2 * i2 + 1];
            }
            float xn = 0.8f * xv + g_Ieff[((size_t)t * BATCH + b) * HID + j] + 0.2f * (w1 + w2);
            xv = xn;
            traj[((size_t)b * TT + t) * HID + j] = xn;
            g_rb[cur ^ 1][b * HID + j] = __float2bfloat16(tanhf(xn));
        }

        // grid barrier (flag + release)
        __syncthreads();
        unsigned v = sbase + t + 1;
        if (tid == 0) { __threadfence(); g_flags[blockIdx.x] = v; }
        if (blockIdx.x == 0) {
            if (tid < NCTA) { while (g_flags[tid] < v) {} }
            __syncthreads();
            if (tid == 0) { __threadfence(); g_rel = v; }
        }
        if (tid == 0) { while (g_rel < v) {} }
        __syncthreads();
        __threadfence();
        cur ^= 1;
    }
    if (tid < 128)
        dout[XF_OFF + (size_t)(tid & 63) * HID + j0 + (tid >> 6)] = xv;
}

__global__ void k_head(const float* __restrict__ wo, const float* __restrict__ wob,
                       float* __restrict__ dout) {
    __shared__ float sh[HID];
    __shared__ float red[256];
    int row = blockIdx.x;
    const float* tr = dout + TRAJ_OFF + (size_t)row * HID;
    int tid = threadIdx.x;
    sh[tid] = tanhf(tr[tid]);
    __syncthreads();
    int o = tid & 31, sl = tid >> 5;
    float p = 0.f;
    const float* w = wo + o * HID + sl * 32;
    const float* s = sh + sl * 32;
    #pragma unroll
    for (int i = 0; i < 32; ++i) p += s[i] * __ldg(&w[i]);
    red[tid] = p;
    __syncthreads();
    if (tid < 32) {
        float s2 = red[tid];
        #pragma unroll
        for (int k = 1; k < 8; ++k) s2 += red[tid + 32 * k];
        dout[(size_t)row * OUTDIM + tid] = s2 + wob[tid];
    }
}

extern "C" void kernel_launch(void* const* d_in, const int* in_sizes, int n_in,
                              void* d_out, int out_size) {
    const float* u      = (const float*)d_in[0];
    const float* x0     = (const float*)d_in[1];
    const float* noise  = (const float*)d_in[2];
    const float* whh    = (const float*)d_in[3];
    const float* wtb    = (const float*)d_in[4];
    const float* winw   = (const float*)d_in[5];
    const float* winb   = (const float*)d_in[6];
    const float* woutw  = (const float*)d_in[7];
    const float* woutb  = (const float*)d_in[8];
    float* dout = (float*)d_out;

    static int smem_set = 0;
    if (!smem_set) {
        cudaFuncSetAttribute(k_main, cudaFuncAttributeMaxDynamicSharedMemorySize, DSMEM);
        smem_set = 1;
    }

    k_init<<<64, 256>>>(x0);
    k_ieff<<<TT, HID>>>(u, noise, winw, winb);
    dim3 gp(136, 256);
    k_pack<<<gp, 256>>>(wtb);
    k_main<<<NCTA, NTHR, DSMEM>>>(whh, x0, dout);
    k_head<<<BATCH * TT, HID>>>(woutw, woutb, dout);
}

// round 16
// speedup vs baseline: 2.8689x; 1.0006x over previous
#include <cuda_runtime.h>
#include <cuda_bf16.h>
#include <cstdint>

#define HID 256
#define BATCH 64
#define TT 256
#define INDIM 64
#define OUTDIM 32
#define OUT_ELEMS (BATCH*TT*OUTDIM)
#define XF_OFF OUT_ELEMS
#define TRAJ_OFF (OUT_ELEMS + BATCH*HID)
#define NCTA 128
#define NTHR 256
#define RS_OFF 139264u
#define DSMEM (139264u + 33792u)   // T tiles + padded rs

__device__ __nv_bfloat16 g_Tb[(size_t)256 * 34816];        // packed sym tiles
__device__ float         g_Ieff[(size_t)TT * BATCH * HID];
__device__ __nv_bfloat16 g_rb[2][BATCH * HID];
__device__ volatile unsigned g_flags[NCTA];
__device__ volatile unsigned g_rel;

__device__ __forceinline__ void mma16816(float c[4], const unsigned a[4], const unsigned b[2]) {
    asm volatile(
        "mma.sync.aligned.m16n8k16.row.col.f32.bf16.bf16.f32 "
        "{%0,%1,%2,%3}, {%4,%5,%6,%7}, {%8,%9}, {%0,%1,%2,%3};\n"
        : "+f"(c[0]), "+f"(c[1]), "+f"(c[2]), "+f"(c[3])
        : "r"(a[0]), "r"(a[1]), "r"(a[2]), "r"(a[3]), "r"(b[0]), "r"(b[1]));
}

__device__ __forceinline__ void ldsm4(unsigned a[4], unsigned addr) {
    asm volatile("ldmatrix.sync.aligned.m8n8.x4.shared.b16 {%0,%1,%2,%3}, [%4];"
        : "=r"(a[0]), "=r"(a[1]), "=r"(a[2]), "=r"(a[3]) : "r"(addr));
}

__device__ __forceinline__ void cp16(char* sm, unsigned off, const void* g) {
    unsigned sa = (unsigned)__cvta_generic_to_shared(sm + off);
    asm volatile("cp.async.cg.shared.global [%0], [%1], 16;\n" :: "r"(sa), "l"(g));
}

__device__ __forceinline__ float dot2f(uint32_t r, float w0, float w1) {
    __nv_bfloat162 q = *(__nv_bfloat162*)&r;
    return __bfloat162float(q.x) * w0 + __bfloat162float(q.y) * w1;
}

__global__ void k_init(const float* __restrict__ x0) {
    int i = blockIdx.x * blockDim.x + threadIdx.x;
    if (i < BATCH * HID) g_rb[0][i] = __float2bfloat16(tanhf(x0[i]));
}

__global__ void k_ieff(const float* __restrict__ u, const float* __restrict__ noise,
                       const float* __restrict__ winw, const float* __restrict__ winb) {
    __shared__ float us[BATCH][INDIM];
    int t = blockIdx.x, h = threadIdx.x;
    for (int idx = h; idx < BATCH * INDIM; idx += blockDim.x) {
        int b = idx / INDIM, in = idx % INDIM;
        us[b][in] = u[((size_t)b * TT + t) * INDIM + in];
    }
    __syncthreads();
    float wreg[INDIM];
    #pragma unroll
    for (int in = 0; in < INDIM; ++in) wreg[in] = winw[h * INDIM + in];
    float bias = winb[h];
    for (int b = 0; b < BATCH; ++b) {
        float acc = bias;
        #pragma unroll
        for (int in = 0; in < INDIM; ++in) acc += us[b][in] * wreg[in];
        size_t off = ((size_t)t * BATCH + b) * HID + h;
        g_Ieff[off] = 0.05f * noise[off] + 0.2f * acc;
    }
}

// pack T[j, tile(I,K)] = (W[j,i,k] + W[j,k,i]) (diag tiles *0.5), transposed [k][i], swizzled
__global__ void k_pack(const float* __restrict__ W) {
    int t = blockIdx.x, j = blockIdx.y;
    int i = threadIdx.x & 15, k = threadIdx.x >> 4;
    int K = 0;
    while ((K + 1) * (K + 2) / 2 <= t) ++K;
    int I = t - K * (K + 1) / 2;
    size_t base = (size_t)j * 65536;
    float v = W[base + (size_t)(I * 16 + i) * 256 + K * 16 + k]
            + W[base + (size_t)(K * 16 + k) * 256 + I * 16 + i];
    if (I == K) v *= 0.5f;
    int iw = (i >> 1) ^ ((k & 4) ? 4 : 0);
    g_Tb[(size_t)j * 34816 + t * 256 + k * 16 + iw * 2 + (i & 1)] = __float2bfloat16(v);
}

__global__ void __launch_bounds__(NTHR, 1)
k_main(const float* __restrict__ whh_g, const float* __restrict__ x0,
       float* __restrict__ dout) {
    extern __shared__ char smem[];
    const uint32_t* Tsm = (const uint32_t*)smem;                // 272 tiles * 128 words
    const uint32_t* rsw = (const uint32_t*)(smem + RS_OFF);     // 64 rows * 132 words (528B)
    __shared__ float reds[8][64];
    __shared__ float whh[2][HID];
    __shared__ unsigned sbase;

    const int tid = threadIdx.x, warp = tid >> 5, lane = tid & 31;
    const int lq = lane >> 2, lr = lane & 3;
    const int j0 = blockIdx.x * 2;
    const int ww = warp & 3, jsel = warp >> 2;
    float* traj = dout + TRAJ_OFF;

    if (tid == 0) sbase = g_rel;
    whh[0][tid] = whh_g[(size_t)j0 * HID + tid];
    whh[1][tid] = whh_g[(size_t)(j0 + 1) * HID + tid];

    // one-time load of T[j0],T[j1] into smem
    {
        const char* src = (const char*)(g_Tb + (size_t)j0 * 34816);
        #pragma unroll
        for (int it = 0; it < 34; ++it) {
            int idx = it * 256 + tid;
            cp16(smem, (unsigned)idx * 16u, src + (size_t)idx * 16);
        }
        asm volatile("cp.async.commit_group;\n" ::);
    }
    float xv = 0.f;
    if (tid < 128) xv = x0[(size_t)(tid & 63) * HID + j0 + (tid >> 6)];

    const int cols[4] = { ww, 15 - ww, ww + 4, 11 - ww };
    const int m4 = (lq & 4) ? 4 : 0;
    // per-lane ldmatrix base address (generic->shared) for rs
    const unsigned rs_shared = (unsigned)__cvta_generic_to_shared(smem + RS_OFF);
    const unsigned lm_base = rs_shared + (unsigned)(lane & 15) * 528u + ((lane & 16) ? 16u : 0u);

    int cur = 0;
    for (int t = 0; t < TT; ++t) {
        // stage r (bf16, padded rows) via cp.async
        const char* src = (const char*)g_rb[cur];
        #pragma unroll
        for (int it = 0; it < 8; ++it) {
            int idx = it * 256 + tid, row = idx >> 5, c = idx & 31;
            cp16(smem, RS_OFF + (unsigned)(row * 528 + c * 16), src + (size_t)idx * 16);
        }
        asm volatile("cp.async.commit_group;\n" ::);
        asm volatile("cp.async.wait_group 0;\n" ::: "memory");
        __syncthreads();

        float acc[4][4][2][4];   // [cc][m][g][frag]
        #pragma unroll
        for (int cc = 0; cc < 4; ++cc)
            #pragma unroll
            for (int m = 0; m < 4; ++m)
                #pragma unroll
                for (int g = 0; g < 2; ++g)
                    #pragma unroll
                    for (int f = 0; f < 4; ++f) acc[cc][m][g][f] = 0.f;

        const uint32_t* tj = Tsm + (size_t)jsel * 136 * 128;

        for (int I = 0; I < 16; ++I) {
            unsigned a[4][4];
            #pragma unroll
            for (int m = 0; m < 4; ++m)
                ldsm4(a[m], lm_base + (unsigned)(m * 16 * 528) + (unsigned)(I * 32));
            #pragma unroll
            for (int cc = 0; cc < 4; ++cc) {
                const int K = cols[cc];
                if (K >= I) {
                    const uint32_t* tw = tj + (K * (K + 1) / 2 + I) * 128;
                    unsigned bf[2][2];
                    bf[0][0] = tw[lq * 8 + (lr ^ m4)];
                    bf[0][1] = tw[lq * 8 + ((lr + 4) ^ m4)];
                    bf[1][0] = tw[(lq + 8) * 8 + (lr ^ m4)];
                    bf[1][1] = tw[(lq + 8) * 8 + ((lr + 4) ^ m4)];
                    #pragma unroll
                    for (int m = 0; m < 4; ++m) {
                        mma16816(acc[cc][m][0], a[m], bf[0]);
                        mma16816(acc[cc][m][1], a[m], bf[1]);
                    }
                }
            }
        }

        // column epilogues: p[b] += y_K[b,:] . r[b, K-block]
        float p[8];
        #pragma unroll
        for (int m = 0; m < 8; ++m) p[m] = 0.f;
        #pragma unroll
        for (int cc = 0; cc < 4; ++cc) {
            const int K = cols[cc];
            #pragma unroll
            for (int m = 0; m < 4; ++m) {
                int b0 = m * 16 + lq;
                #pragma unroll
                for (int g = 0; g < 2; ++g) {
                    uint32_t rv0 = rsw[b0 * 132 + K * 8 + g * 4 + lr];
                    uint32_t rv1 = rsw[(b0 + 8) * 132 + K * 8 + g * 4 + lr];
                    __nv_bfloat162 q0 = *(__nv_bfloat162*)&rv0;
                    __nv_bfloat162 q1 = *(__nv_bfloat162*)&rv1;
                    p[2 * m]     += acc[cc][m][g][0] * __bfloat162float(q0.x) + acc[cc][m][g][1] * __bfloat162float(q0.y);
                    p[2 * m + 1] += acc[cc][m][g][2] * __bfloat162float(q1.x) + acc[cc][m][g][3] * __bfloat162float(q1.y);
                }
            }
        }
        #pragma unroll
        for (int m = 0; m < 8; ++m) {
            p[m] += __shfl_xor_sync(0xFFFFFFFFu, p[m], 1);
            p[m] += __shfl_xor_sync(0xFFFFFFFFu, p[m], 2);
        }
        if (lr == 0) {
            #pragma unroll
            for (int m = 0; m < 4; ++m) {
                reds[warp][m * 16 + lq]     = p[2 * m];
                reds[warp][m * 16 + lq + 8] = p[2 * m + 1];
            }
        }
        __syncthreads();

        // W1 (uint4 loads) + state update
        if (tid < 128) {
            int jj = tid >> 6, b = tid & 63, j = j0 + jj;
            float w2 = reds[jj * 4][b] + reds[jj * 4 + 1][b] + reds[jj * 4 + 2][b] + reds[jj * 4 + 3][b];
            float w1 = 0.f;
            const uint4* rrow4 = (const uint4*)(smem + RS_OFF) + b * 33;
            const float4* wh4 = (const float4*)whh[jj];
            #pragma unroll 8
            for (int c = 0; c < 32; ++c) {
                uint4 rv = rrow4[c];
                float4 wa = wh4[2 * c], wb = wh4[2 * c + 1];
                w1 += dot2f(rv.x, wa.x, wa.y) + dot2f(rv.y, wa.z, wa.w)
                    + dot2f(rv.z, wb.x, wb.y) + dot2f(rv.w, wb.z, wb.w);
            }
            float xn = 0.8f * xv + g_Ieff[((size_t)t * BATCH + b) * HID + j] + 0.2f * (w1 + w2);
            xv = xn;
            traj[((size_t)b * TT + t) * HID + j] = xn;
            g_rb[cur ^ 1][b * HID + j] = __float2bfloat16(tanhf(xn));
            __threadfence();
        }

        // grid barrier (flag + release)
        __syncthreads();
        unsigned v = sbase + t + 1;
        if (tid == 0) { g_flags[blockIdx.x] = v; }
        if (blockIdx.x == 0) {
            if (tid < NCTA) { while (g_flags[tid] < v) {} }
            __syncthreads();
            if (tid == 0) { __threadfence(); g_rel = v; }
        }
        if (tid == 0) { while (g_rel < v) {} }
        __syncthreads();
        __threadfence();
        cur ^= 1;
    }
    if (tid < 128)
        dout[XF_OFF + (size_t)(tid & 63) * HID + j0 + (tid >> 6)] = xv;
}

__global__ void k_head(const float* __restrict__ wo, const float* __restrict__ wob,
                       float* __restrict__ dout) {
    __shared__ float sh[HID];
    __shared__ float red[256];
    int row = blockIdx.x;
    const float* tr = dout + TRAJ_OFF + (size_t)row * HID;
    int tid = threadIdx.x;
    sh[tid] = tanhf(tr[tid]);
    __syncthreads();
    int o = tid & 31, sl = tid >> 5;
    float p = 0.f;
    const float* w = wo + o * HID + sl * 32;
    const float* s = sh + sl * 32;
    #pragma unroll
    for (int i = 0; i < 32; ++i) p += s[i] * __ldg(&w[i]);
    red[tid] = p;
    __syncthreads();
    if (tid < 32) {
        float s2 = red[tid];
        #pragma unroll
        for (int k = 1; k < 8; ++k) s2 += red[tid + 32 * k];
        dout[(size_t)row * OUTDIM + tid] = s2 + wob[tid];
    }
}

extern "C" void kernel_launch(void* const* d_in, const int* in_sizes, int n_in,
                              void* d_out, int out_size) {
    const float* u      = (const float*)d_in[0];
    const float* x0     = (const float*)d_in[1];
    const float* noise  = (const float*)d_in[2];
    const float* whh    = (const float*)d_in[3];
    const float* wtb    = (const float*)d_in[4];
    const float* winw   = (const float*)d_in[5];
    const float* winb   = (const float*)d_in[6];
    const float* woutw  = (const float*)d_in[7];
    const float* woutb  = (const float*)d_in[8];
    float* dout = (float*)d_out;

    static int smem_set = 0;
    if (!smem_set) {
        cudaFuncSetAttribute(k_main, cudaFuncAttributeMaxDynamicSharedMemorySize, DSMEM);
        smem_set = 1;
    }

    k_init<<<64, 256>>>(x0);
    k_ieff<<<TT, HID>>>(u, noise, winw, winb);
    dim3 gp(136, 256);
    k_pack<<<gp, 256>>>(wtb);
    k_main<<<NCTA, NTHR, DSMEM>>>(whh, x0, dout);
    k_head<<<BATCH * TT, HID>>>(woutw, woutb, dout);
}

// round 17
// speedup vs baseline: 3.0473x; 1.0622x over previous
#include <cuda_runtime.h>
#include <cuda_bf16.h>
#include <cstdint>

#define HID 256
#define BATCH 64
#define TT 256
#define INDIM 64
#define OUTDIM 32
#define OUT_ELEMS (BATCH*TT*OUTDIM)
#define XF_OFF OUT_ELEMS
#define TRAJ_OFF (OUT_ELEMS + BATCH*HID)
#define NCTA 128
#define NTHR 512
#define RS_OFF 139264u
#define DSMEM (139264u + 33792u)   // T tiles + padded rs

__device__ __nv_bfloat16 g_Tb[(size_t)256 * 34816];        // packed sym tiles
__device__ float         g_Ieff[(size_t)TT * BATCH * HID];
__device__ __nv_bfloat16 g_rb[2][BATCH * HID];
__device__ volatile unsigned g_flags[NCTA];
__device__ volatile unsigned g_rel;

__device__ __forceinline__ void mma16816(float c[4], const unsigned a[4], const unsigned b[2]) {
    asm volatile(
        "mma.sync.aligned.m16n8k16.row.col.f32.bf16.bf16.f32 "
        "{%0,%1,%2,%3}, {%4,%5,%6,%7}, {%8,%9}, {%0,%1,%2,%3};\n"
        : "+f"(c[0]), "+f"(c[1]), "+f"(c[2]), "+f"(c[3])
        : "r"(a[0]), "r"(a[1]), "r"(a[2]), "r"(a[3]), "r"(b[0]), "r"(b[1]));
}

__device__ __forceinline__ void ldsm4(unsigned a[4], unsigned addr) {
    asm volatile("ldmatrix.sync.aligned.m8n8.x4.shared.b16 {%0,%1,%2,%3}, [%4];"
        : "=r"(a[0]), "=r"(a[1]), "=r"(a[2]), "=r"(a[3]) : "r"(addr));
}

__device__ __forceinline__ void cp16(char* sm, unsigned off, const void* g) {
    unsigned sa = (unsigned)__cvta_generic_to_shared(sm + off);
    asm volatile("cp.async.cg.shared.global [%0], [%1], 16;\n" :: "r"(sa), "l"(g));
}

__device__ __forceinline__ float dot2f(uint32_t r, float w0, float w1) {
    __nv_bfloat162 q = *(__nv_bfloat162*)&r;
    return __bfloat162float(q.x) * w0 + __bfloat162float(q.y) * w1;
}

__global__ void k_init(const float* __restrict__ x0) {
    int i = blockIdx.x * blockDim.x + threadIdx.x;
    if (i < BATCH * HID) g_rb[0][i] = __float2bfloat16(tanhf(x0[i]));
}

__global__ void k_ieff(const float* __restrict__ u, const float* __restrict__ noise,
                       const float* __restrict__ winw, const float* __restrict__ winb) {
    __shared__ float us[BATCH][INDIM];
    int t = blockIdx.x, h = threadIdx.x;
    for (int idx = h; idx < BATCH * INDIM; idx += blockDim.x) {
        int b = idx / INDIM, in = idx % INDIM;
        us[b][in] = u[((size_t)b * TT + t) * INDIM + in];
    }
    __syncthreads();
    float wreg[INDIM];
    #pragma unroll
    for (int in = 0; in < INDIM; ++in) wreg[in] = winw[h * INDIM + in];
    float bias = winb[h];
    for (int b = 0; b < BATCH; ++b) {
        float acc = bias;
        #pragma unroll
        for (int in = 0; in < INDIM; ++in) acc += us[b][in] * wreg[in];
        size_t off = ((size_t)t * BATCH + b) * HID + h;
        g_Ieff[off] = 0.05f * noise[off] + 0.2f * acc;
    }
}

// pack T[j, tile(I,K)] = (W[j,i,k] + W[j,k,i]) (diag tiles *0.5), transposed [k][i], swizzled
__global__ void k_pack(const float* __restrict__ W) {
    int t = blockIdx.x, j = blockIdx.y;
    int i = threadIdx.x & 15, k = threadIdx.x >> 4;
    int K = 0;
    while ((K + 1) * (K + 2) / 2 <= t) ++K;
    int I = t - K * (K + 1) / 2;
    size_t base = (size_t)j * 65536;
    float v = W[base + (size_t)(I * 16 + i) * 256 + K * 16 + k]
            + W[base + (size_t)(K * 16 + k) * 256 + I * 16 + i];
    if (I == K) v *= 0.5f;
    int iw = (i >> 1) ^ ((k & 4) ? 4 : 0);
    g_Tb[(size_t)j * 34816 + t * 256 + k * 16 + iw * 2 + (i & 1)] = __float2bfloat16(v);
}

__global__ void __launch_bounds__(NTHR, 1)
k_main(const float* __restrict__ whh_g, const float* __restrict__ x0,
       float* __restrict__ dout) {
    extern __shared__ char smem[];
    const uint32_t* Tsm = (const uint32_t*)smem;                // 272 tiles * 128 words
    const uint32_t* rsw = (const uint32_t*)(smem + RS_OFF);     // 64 rows * 132 words (528B)
    __shared__ float reds[16][64];
    __shared__ float whh[2][HID];
    __shared__ unsigned sbase;

    const int tid = threadIdx.x, warp = tid >> 5, lane = tid & 31;
    const int lq = lane >> 2, lr = lane & 3;
    const int j0 = blockIdx.x * 2;
    const int ww = warp & 7, jsel = warp >> 3;
    float* traj = dout + TRAJ_OFF;

    if (tid == 0) sbase = g_rel;
    if (tid < 512) {
        int jj = tid >> 8, h = tid & 255;
        whh[jj][h] = whh_g[(size_t)(j0 + jj) * HID + h];
    }

    // one-time load of T[j0],T[j1] into smem (8704 x 16B)
    {
        const char* src = (const char*)(g_Tb + (size_t)j0 * 34816);
        #pragma unroll
        for (int it = 0; it < 17; ++it) {
            int idx = it * 512 + tid;
            cp16(smem, (unsigned)idx * 16u, src + (size_t)idx * 16);
        }
        asm volatile("cp.async.commit_group;\n" ::);
    }
    float xv = 0.f;
    if (tid < 128) xv = x0[(size_t)(tid & 63) * HID + j0 + (tid >> 6)];

    const int K0 = ww, K1 = 15 - ww;   // column pair; tiles (K0+1)+(K1+1) = 17
    const int m4 = (lq & 4) ? 4 : 0;
    const unsigned rs_shared = (unsigned)__cvta_generic_to_shared(smem + RS_OFF);
    const unsigned lm_base = rs_shared + (unsigned)(lane & 15) * 528u + ((lane & 16) ? 16u : 0u);
    const uint32_t* tj = Tsm + (size_t)jsel * 136 * 128;
    const uint32_t* t0 = tj + (K0 * (K0 + 1) / 2) * 128;
    const uint32_t* t1 = tj + (K1 * (K1 + 1) / 2) * 128;

    int cur = 0;
    for (int t = 0; t < TT; ++t) {
        // stage r (bf16, padded rows) via cp.async: 2048 x 16B
        const char* src = (const char*)g_rb[cur];
        #pragma unroll
        for (int it = 0; it < 4; ++it) {
            int idx = it * 512 + tid, row = idx >> 5, c = idx & 31;
            cp16(smem, RS_OFF + (unsigned)(row * 528 + c * 16), src + (size_t)idx * 16);
        }
        asm volatile("cp.async.commit_group;\n" ::);
        asm volatile("cp.async.wait_group 0;\n" ::: "memory");
        __syncthreads();

        // prefetch Ieff for update threads (off critical path)
        float ie = 0.f;
        if (tid < 128)
            ie = g_Ieff[((size_t)t * BATCH + (tid & 63)) * HID + j0 + (tid >> 6)];

        float acc[2][4][2][4];   // [cc][m][g][frag]
        #pragma unroll
        for (int cc = 0; cc < 2; ++cc)
            #pragma unroll
            for (int m = 0; m < 4; ++m)
                #pragma unroll
                for (int g = 0; g < 2; ++g)
                    #pragma unroll
                    for (int f = 0; f < 4; ++f) acc[cc][m][g][f] = 0.f;

        for (int I = 0; I <= K1; ++I) {
            unsigned a[4][4];
            #pragma unroll
            for (int m = 0; m < 4; ++m)
                ldsm4(a[m], lm_base + (unsigned)(m * 16 * 528) + (unsigned)(I * 32));
            if (I <= K0) {
                const uint32_t* tw = t0 + I * 128;
                unsigned bf[2][2];
                bf[0][0] = tw[lq * 8 + (lr ^ m4)];
                bf[0][1] = tw[lq * 8 + ((lr + 4) ^ m4)];
                bf[1][0] = tw[(lq + 8) * 8 + (lr ^ m4)];
                bf[1][1] = tw[(lq + 8) * 8 + ((lr + 4) ^ m4)];
                #pragma unroll
                for (int m = 0; m < 4; ++m) {
                    mma16816(acc[0][m][0], a[m], bf[0]);
                    mma16816(acc[0][m][1], a[m], bf[1]);
                }
            }
            {
                const uint32_t* tw = t1 + I * 128;
                unsigned bf[2][2];
                bf[0][0] = tw[lq * 8 + (lr ^ m4)];
                bf[0][1] = tw[lq * 8 + ((lr + 4) ^ m4)];
                bf[1][0] = tw[(lq + 8) * 8 + (lr ^ m4)];
                bf[1][1] = tw[(lq + 8) * 8 + ((lr + 4) ^ m4)];
                #pragma unroll
                for (int m = 0; m < 4; ++m) {
                    mma16816(acc[1][m][0], a[m], bf[0]);
                    mma16816(acc[1][m][1], a[m], bf[1]);
                }
            }
        }

        // column epilogues: p[b] += y_K[b,:] . r[b, K-block]
        float p[8];
        #pragma unroll
        for (int m = 0; m < 8; ++m) p[m] = 0.f;
        #pragma unroll
        for (int cc = 0; cc < 2; ++cc) {
            const int K = cc ? K1 : K0;
            #pragma unroll
            for (int m = 0; m < 4; ++m) {
                int b0 = m * 16 + lq;
                #pragma unroll
                for (int g = 0; g < 2; ++g) {
                    uint32_t rv0 = rsw[b0 * 132 + K * 8 + g * 4 + lr];
                    uint32_t rv1 = rsw[(b0 + 8) * 132 + K * 8 + g * 4 + lr];
                    __nv_bfloat162 q0 = *(__nv_bfloat162*)&rv0;
                    __nv_bfloat162 q1 = *(__nv_bfloat162*)&rv1;
                    p[2 * m]     += acc[cc][m][g][0] * __bfloat162float(q0.x) + acc[cc][m][g][1] * __bfloat162float(q0.y);
                    p[2 * m + 1] += acc[cc][m][g][2] * __bfloat162float(q1.x) + acc[cc][m][g][3] * __bfloat162float(q1.y);
                }
            }
        }
        #pragma unroll
        for (int m = 0; m < 8; ++m) {
            p[m] += __shfl_xor_sync(0xFFFFFFFFu, p[m], 1);
            p[m] += __shfl_xor_sync(0xFFFFFFFFu, p[m], 2);
        }
        if (lr == 0) {
            #pragma unroll
            for (int m = 0; m < 4; ++m) {
                reds[warp][m * 16 + lq]     = p[2 * m];
                reds[warp][m * 16 + lq + 8] = p[2 * m + 1];
            }
        }
        __syncthreads();

        // W1 (uint4 loads) + state update
        if (tid < 128) {
            int jj = tid >> 6, b = tid & 63, j = j0 + jj;
            float w2 = 0.f;
            #pragma unroll
            for (int w = 0; w < 8; ++w) w2 += reds[jj * 8 + w][b];
            float w1 = 0.f;
            const uint4* rrow4 = (const uint4*)(smem + RS_OFF) + b * 33;
            const float4* wh4 = (const float4*)whh[jj];
            #pragma unroll 8
            for (int c = 0; c < 32; ++c) {
                uint4 rv = rrow4[c];
                float4 wa = wh4[2 * c], wb = wh4[2 * c + 1];
                w1 += dot2f(rv.x, wa.x, wa.y) + dot2f(rv.y, wa.z, wa.w)
                    + dot2f(rv.z, wb.x, wb.y) + dot2f(rv.w, wb.z, wb.w);
            }
            float xn = 0.8f * xv + ie + 0.2f * (w1 + w2);
            xv = xn;
            traj[((size_t)b * TT + t) * HID + j] = xn;
            g_rb[cur ^ 1][b * HID + j] = __float2bfloat16(tanhf(xn));
            __threadfence();
        }

        // grid barrier (flag + release)
        __syncthreads();
        unsigned v = sbase + t + 1;
        if (tid == 0) { g_flags[blockIdx.x] = v; }
        if (blockIdx.x == 0) {
            if (tid < NCTA) { while (g_flags[tid] < v) {} }
            __syncthreads();
            if (tid == 0) { __threadfence(); g_rel = v; }
        }
        if (tid == 0) { while (g_rel < v) {} }
        __syncthreads();
        __threadfence();
        cur ^= 1;
    }
    if (tid < 128)
        dout[XF_OFF + (size_t)(tid & 63) * HID + j0 + (tid >> 6)] = xv;
}

__global__ void k_head(const float* __restrict__ wo, const float* __restrict__ wob,
                       float* __restrict__ dout) {
    __shared__ float sh[HID];
    __shared__ float red[256];
    int row = blockIdx.x;
    const float* tr = dout + TRAJ_OFF + (size_t)row * HID;
    int tid = threadIdx.x;
    sh[tid] = tanhf(tr[tid]);
    __syncthreads();
    int o = tid & 31, sl = tid >> 5;
    float p = 0.f;
    const float* w = wo + o * HID + sl * 32;
    const float* s = sh + sl * 32;
    #pragma unroll
    for (int i = 0; i < 32; ++i) p += s[i] * __ldg(&w[i]);
    red[tid] = p;
    __syncthreads();
    if (tid < 32) {
        float s2 = red[tid];
        #pragma unroll
        for (int k = 1; k < 8; ++k) s2 += red[tid + 32 * k];
        dout[(size_t)row * OUTDIM + tid] = s2 + wob[tid];
    }
}

extern "C" void kernel_launch(void* const* d_in, const int* in_sizes, int n_in,
                              void* d_out, int out_size) {
    const float* u      = (const float*)d_in[0];
    const float* x0     = (const float*)d_in[1];
    const float* noise  = (const float*)d_in[2];
    const float* whh    = (const float*)d_in[3];
    const float* wtb    = (const float*)d_in[4];
    const float* winw   = (const float*)d_in[5];
    const float* winb   = (const float*)d_in[6];
    const float* woutw  = (const float*)d_in[7];
    const float* woutb  = (const float*)d_in[8];
    float* dout = (float*)d_out;

    static int smem_set = 0;
    if (!smem_set) {
        cudaFuncSetAttribute(k_main, cudaFuncAttributeMaxDynamicSharedMemorySize, DSMEM);
        smem_set = 1;
    }

    k_init<<<64, 256>>>(x0);
    k_ieff<<<TT, HID>>>(u, noise, winw, winb);
    dim3 gp(136, 256);
    k_pack<<<gp, 256>>>(wtb);
    k_main<<<NCTA, NTHR, DSMEM>>>(whh, x0, dout);
    k_head<<<BATCH * TT, HID>>>(woutw, woutb, dout);
}